// round 3
// baseline (speedup 1.0000x reference)
#include <cuda_runtime.h>
#include <cuda_bf16.h>

#define COLS  4096
#define TPB   512
#define EPT   8     // elements per thread = 2 x float4
#define NWARP (TPB / 32)

__device__ __forceinline__ float fsign(float x) {
    return (x > 0.f) ? 1.f : ((x < 0.f) ? -1.f : 0.f);
}

// Block-wide sum of one value, broadcast to all threads.
__device__ __forceinline__ float block_reduce(float a) {
    __shared__ float sw[NWARP];
    #pragma unroll
    for (int o = 16; o; o >>= 1) a += __shfl_xor_sync(0xffffffffu, a, o);
    const int w = threadIdx.x >> 5;
    if ((threadIdx.x & 31) == 0) sw[w] = a;
    __syncthreads();
    if (threadIdx.x < 32) {
        a = (threadIdx.x < NWARP) ? sw[threadIdx.x] : 0.f;
        #pragma unroll
        for (int o = NWARP / 2; o; o >>= 1) a += __shfl_xor_sync(0xffffffffu, a, o);
        if (threadIdx.x == 0) sw[0] = a;
    }
    __syncthreads();
    float r = sw[0];
    __syncthreads();   // protect smem reuse across successive calls
    return r;
}

// Block-wide sum of a pair, broadcast to all threads.
__device__ __forceinline__ float2 block_reduce2(float a, float b) {
    __shared__ float sa[NWARP], sb[NWARP];
    #pragma unroll
    for (int o = 16; o; o >>= 1) {
        a += __shfl_xor_sync(0xffffffffu, a, o);
        b += __shfl_xor_sync(0xffffffffu, b, o);
    }
    const int w = threadIdx.x >> 5;
    if ((threadIdx.x & 31) == 0) { sa[w] = a; sb[w] = b; }
    __syncthreads();
    if (threadIdx.x < 32) {
        a = (threadIdx.x < NWARP) ? sa[threadIdx.x] : 0.f;
        b = (threadIdx.x < NWARP) ? sb[threadIdx.x] : 0.f;
        #pragma unroll
        for (int o = NWARP / 2; o; o >>= 1) {
            a += __shfl_xor_sync(0xffffffffu, a, o);
            b += __shfl_xor_sync(0xffffffffu, b, o);
        }
        if (threadIdx.x == 0) { sa[0] = a; sb[0] = b; }
    }
    __syncthreads();
    float2 r = make_float2(sa[0], sb[0]);
    __syncthreads();
    return r;
}

__global__ __launch_bounds__(TPB) void braq_order2_kernel(
    const float* __restrict__ x,
    const int* __restrict__ mask,
    float* __restrict__ out)
{
    const size_t base = (size_t)blockIdx.x * COLS;
    const float4* __restrict__ x4 = reinterpret_cast<const float4*>(x + base);
    const int4*   __restrict__ m4 = reinterpret_cast<const int4*>(mask + base);

    float v[EPT];    // masked x, later reused to hold b1
    float mf[EPT];   // mask as float {0,1}
    float r2[EPT];   // second-order residual (masked)

    // ---- load + pass 1 partials: sum, count (all masking via FMUL) ----
    float s = 0.f, c = 0.f;
    #pragma unroll
    for (int i = 0; i < EPT / 4; i++) {
        const int idx = threadIdx.x + i * TPB;
        float4 xv = __ldg(&x4[idx]);
        int4   mv = __ldg(&m4[idx]);
        const float xs[4] = {xv.x, xv.y, xv.z, xv.w};
        const int   ms[4] = {mv.x, mv.y, mv.z, mv.w};
        #pragma unroll
        for (int j = 0; j < 4; j++) {
            const int k = i * 4 + j;
            const float m = (ms[j] != 0) ? 1.f : 0.f;
            const float val = xs[j] * m;
            mf[k] = m;
            v[k]  = val;
            s += val;
            c += m;
        }
    }

    float2 r1 = block_reduce2(s, c);
    const float inv   = (r1.y > 0.f) ? (1.f / r1.y) : 0.f;  // empty-row safe
    const float mean1 = r1.x * inv;

    // ---- pass 2: scale1 = mean |masked(v - mean1)| ----
    float a = 0.f;
    #pragma unroll
    for (int k = 0; k < EPT; k++)
        a += fabsf(v[k] - mean1) * mf[k];
    const float scale1 = block_reduce(a) * inv;

    // ---- compute b1, r2 ONCE per element ----
    float s2 = 0.f;
    #pragma unroll
    for (int k = 0; k < EPT; k++) {
        const float d  = v[k] - mean1;
        const float b1 = fsign(d) * scale1 + mean1;
        const float r  = (v[k] - b1) * mf[k];
        v[k]  = b1;   // reuse
        r2[k] = r;
        s2 += r;
    }
    const float mean2 = block_reduce(s2) * inv;

    // ---- pass 4: scale2 = mean |masked(r2 - mean2)| ----
    float a2 = 0.f;
    #pragma unroll
    for (int k = 0; k < EPT; k++)
        a2 += fabsf(r2[k] - mean2) * mf[k];
    const float scale2 = block_reduce(a2) * inv;

    // ---- output: mf * (b1 + sign(c2)*scale2 + mean2) ----
    float4* __restrict__ o4 = reinterpret_cast<float4*>(out + base);
    #pragma unroll
    for (int i = 0; i < EPT / 4; i++) {
        float t[4];
        #pragma unroll
        for (int j = 0; j < 4; j++) {
            const int k = i * 4 + j;
            const float c2 = r2[k] - mean2;
            t[j] = (v[k] + fsign(c2) * scale2 + mean2) * mf[k];
        }
        float4 ov; ov.x = t[0]; ov.y = t[1]; ov.z = t[2]; ov.w = t[3];
        o4[threadIdx.x + i * TPB] = ov;
    }
}

extern "C" void kernel_launch(void* const* d_in, const int* in_sizes, int n_in,
                              void* d_out, int out_size) {
    const float* x    = (const float*)d_in[0];
    const int*   mask = (const int*)d_in[1];
    float*       out  = (float*)d_out;
    const int rows = in_sizes[0] / COLS;   // 11008
    braq_order2_kernel<<<rows, TPB>>>(x, mask, out);
}